// round 13
// baseline (speedup 1.0000x reference)
#include <cuda_runtime.h>
#include <cuda_fp16.h>
#include <math.h>
#include <stdint.h>

#define D 128
#define NMAX 100000
#define EMAX 1600000
#define BCAP 64          // fixed bucket capacity (Poisson(16); P(overflow)~2e-13)

// ---- device scratch (no allocations allowed) -------------------------------
__device__ __half g_support_h[(size_t)NMAX * D];     // 25.6 MB fp16 support
__device__ int    g_cnt[NMAX];                       // bucket fill counts
__device__ int2   g_bkt[(size_t)NMAX * BCAP];        // 51.2 MB (col, val-bits)
__device__ __half g_Wh[D * D];                       // fp16 W, [k][n]

// ---------------------------------------------------------------------------
__device__ __forceinline__ uint32_t smem_u32(const void* p) {
    uint32_t a;
    asm("{ .reg .u64 t; cvta.to.shared.u64 t, %1; cvt.u32.u64 %0, t; }"
        : "=r"(a) : "l"(p));
    return a;
}
__device__ __forceinline__ float tanh_fast(float x) {
    float y;
    asm("tanh.approx.f32 %0, %1;" : "=f"(y) : "f"(x));
    return y;
}
union F2U { float2 f; unsigned long long u; };

// ---------------------------------------------------------------------------
// W prep: fp32 -> fp16 (runs on GEMM stream, off the CSR critical path)
// ---------------------------------------------------------------------------
__global__ void gcn_wprep_kernel(const float* __restrict__ W)
{
    const int i = blockIdx.x * blockDim.x + threadIdx.x;
    if (i < D * D) g_Wh[i] = __float2half_rn(W[i]);
}

// ---------------------------------------------------------------------------
// GEMM: support = fp16( x @ W ) via HMMA mma.sync.m16n8k16.  (unchanged)
// ---------------------------------------------------------------------------
#define ASTRIDE 136

__global__ void __launch_bounds__(256)
gcn_gemm_kernel(const float* __restrict__ x, int n)
{
    extern __shared__ __half sh[];
    __half* As = sh;                    // 128 * 136
    __half* Ws = sh + 128 * ASTRIDE;    // 128 * 136

    const int tid  = threadIdx.x;
    const int lane = tid & 31;
    const int warp = tid >> 5;
    const int row0 = blockIdx.x * 128;

    {
        const int r = tid >> 1;
        const int h = tid & 1;
        const bool valid = (row0 + r) < n;
        const float4* src = (const float4*)(x + (size_t)(row0 + r) * D + h * 64);
        uint4* dst = (uint4*)(As + r * ASTRIDE + h * 64);
        #pragma unroll
        for (int g = 0; g < 8; g++) {
            float4 v0 = make_float4(0.f, 0.f, 0.f, 0.f), v1 = v0;
            if (valid) { v0 = src[2 * g]; v1 = src[2 * g + 1]; }
            uint4 o;
            __half2 t;
            t = __float22half2_rn(make_float2(v0.x, v0.y)); o.x = *(uint32_t*)&t;
            t = __float22half2_rn(make_float2(v0.z, v0.w)); o.y = *(uint32_t*)&t;
            t = __float22half2_rn(make_float2(v1.x, v1.y)); o.z = *(uint32_t*)&t;
            t = __float22half2_rn(make_float2(v1.z, v1.w)); o.w = *(uint32_t*)&t;
            dst[g] = o;
        }
    }
    {
        const int r = tid >> 1;
        const int h = tid & 1;
        const uint4* src = (const uint4*)(g_Wh + r * D + h * 64);
        uint4* dst = (uint4*)(Ws + r * ASTRIDE + h * 64);
        #pragma unroll
        for (int g = 0; g < 8; g++) dst[g] = src[g];
    }
    __syncthreads();

    float acc[16][4];
    #pragma unroll
    for (int j = 0; j < 16; j++)
        acc[j][0] = acc[j][1] = acc[j][2] = acc[j][3] = 0.f;

    const int ar = warp * 16 + (lane & 15);
    const int ac8 = (lane >> 4) * 8;

    #pragma unroll
    for (int ks = 0; ks < 8; ks++) {
        const int k0 = ks * 16;
        uint32_t a0, a1, a2, a3;
        {
            const uint32_t addr = smem_u32(As + ar * ASTRIDE + k0 + ac8);
            asm volatile("ldmatrix.sync.aligned.m8n8.x4.shared.b16 {%0,%1,%2,%3}, [%4];"
                         : "=r"(a0), "=r"(a1), "=r"(a2), "=r"(a3) : "r"(addr));
        }
        const uint32_t baddr0 = smem_u32(Ws + (k0 + (lane & 15)) * ASTRIDE + ac8);
        #pragma unroll
        for (int j2 = 0; j2 < 8; j2++) {
            uint32_t b0, b1, b2, b3;
            asm volatile("ldmatrix.sync.aligned.m8n8.x4.trans.shared.b16 {%0,%1,%2,%3}, [%4];"
                         : "=r"(b0), "=r"(b1), "=r"(b2), "=r"(b3)
                         : "r"(baddr0 + j2 * 32));
            float* c0 = acc[2 * j2];
            float* c1 = acc[2 * j2 + 1];
            asm volatile(
                "mma.sync.aligned.m16n8k16.row.col.f32.f16.f16.f32 "
                "{%0,%1,%2,%3}, {%4,%5,%6,%7}, {%8,%9}, {%0,%1,%2,%3};"
                : "+f"(c0[0]), "+f"(c0[1]), "+f"(c0[2]), "+f"(c0[3])
                : "r"(a0), "r"(a1), "r"(a2), "r"(a3), "r"(b0), "r"(b1));
            asm volatile(
                "mma.sync.aligned.m16n8k16.row.col.f32.f16.f16.f32 "
                "{%0,%1,%2,%3}, {%4,%5,%6,%7}, {%8,%9}, {%0,%1,%2,%3};"
                : "+f"(c1[0]), "+f"(c1[1]), "+f"(c1[2]), "+f"(c1[3])
                : "r"(a0), "r"(a1), "r"(a2), "r"(a3), "r"(b2), "r"(b3));
        }
    }

    const int rA = row0 + warp * 16 + (lane >> 2);
    const int cB = (lane & 3) * 2;
    #pragma unroll
    for (int j = 0; j < 16; j++) {
        const int n0 = j * 8;
        if (rA < n) {
            __half2 h = __float22half2_rn(make_float2(acc[j][0], acc[j][1]));
            *(__half2*)(g_support_h + (size_t)rA * D + n0 + cB) = h;
        }
        if (rA + 8 < n) {
            __half2 h = __float22half2_rn(make_float2(acc[j][2], acc[j][3]));
            *(__half2*)(g_support_h + (size_t)(rA + 8) * D + n0 + cB) = h;
        }
    }
}

// ---------------------------------------------------------------------------
// fill: direct bucket scatter, 4 independent edges per thread (atomic MLP=4)
// ---------------------------------------------------------------------------
__global__ void gcn_fill_kernel(const int* __restrict__ erow,
                                const int* __restrict__ ecol,
                                const float* __restrict__ eval_, int nE)
{
    const int q = (nE + 3) >> 2;
    const int e = blockIdx.x * blockDim.x + threadIdx.x;
    if (e >= q) return;

    int   r[4];
    int   c[4];
    float f[4];
    bool  vld[4];
    #pragma unroll
    for (int k = 0; k < 4; k++) {
        const int ek = e + k * q;
        vld[k] = ek < nE;
        if (vld[k]) {
            r[k] = __ldg(&erow[ek]);
            c[k] = __ldg(&ecol[ek]);
            f[k] = __ldg(&eval_[ek]);
        }
    }
    int p[4];
    #pragma unroll
    for (int k = 0; k < 4; k++)
        if (vld[k]) p[k] = atomicAdd(&g_cnt[r[k]], 1);
    #pragma unroll
    for (int k = 0; k < 4; k++)
        if (vld[k]) g_bkt[(size_t)r[k] * BCAP + p[k]] = make_int2(c[k], __float_as_int(f[k]));
}

// ---------------------------------------------------------------------------
// Aggregate v4: warp per row, full warp per edge, lane owns 4 cols.
// uint4 metadata loads (2 edges per LDG.128), TWO independent accumulator
// sets (break the FFMA2 serial chain), fused tanh.approx.
// ---------------------------------------------------------------------------
__device__ __forceinline__ void accp(const uint2 u, const uint32_t vbits,
                                     unsigned long long& p0,
                                     unsigned long long& p1)
{
    const float v = __uint_as_float(vbits);
    F2U vv; vv.f = make_float2(v, v);
    F2U f0; f0.f = __half22float2(*(const __half2*)&u.x);
    F2U f1; f1.f = __half22float2(*(const __half2*)&u.y);
    asm("fma.rn.f32x2 %0, %1, %2, %0;" : "+l"(p0) : "l"(vv.u), "l"(f0.u));
    asm("fma.rn.f32x2 %0, %1, %2, %0;" : "+l"(p1) : "l"(vv.u), "l"(f1.u));
}

__global__ void __launch_bounds__(256)
gcn_aggregate_kernel(float* __restrict__ out, int n)
{
    const int r = blockIdx.x * 8 + (threadIdx.x >> 5);
    const int lane = threadIdx.x & 31;
    if (r >= n) return;

    int cnt = g_cnt[r];
    if (cnt > BCAP) cnt = BCAP;
    const uint4* bkt4 = (const uint4*)(g_bkt + (size_t)r * BCAP); // 2 edges/elem
    const __half* sp = g_support_h + lane * 4;       // lane's 4-col slice

    unsigned long long p0a = 0ull, p1a = 0ull;       // set A
    unsigned long long p0b = 0ull, p1b = 0ull;       // set B

    int j = 0;
    for (; j + 4 <= cnt; j += 4) {
        const uint4 m0 = __ldg(&bkt4[(j >> 1)]);     // edges j, j+1
        const uint4 m1 = __ldg(&bkt4[(j >> 1) + 1]); // edges j+2, j+3
        const uint2 u0 = *(const uint2*)(sp + (size_t)m0.x * D);
        const uint2 u1 = *(const uint2*)(sp + (size_t)m0.z * D);
        const uint2 u2 = *(const uint2*)(sp + (size_t)m1.x * D);
        const uint2 u3 = *(const uint2*)(sp + (size_t)m1.z * D);
        accp(u0, m0.y, p0a, p1a);
        accp(u1, m0.w, p0b, p1b);
        accp(u2, m1.y, p0a, p1a);
        accp(u3, m1.w, p0b, p1b);
    }
    if (j + 2 <= cnt) {
        const uint4 m0 = __ldg(&bkt4[(j >> 1)]);
        const uint2 u0 = *(const uint2*)(sp + (size_t)m0.x * D);
        const uint2 u1 = *(const uint2*)(sp + (size_t)m0.z * D);
        accp(u0, m0.y, p0a, p1a);
        accp(u1, m0.w, p0b, p1b);
        j += 2;
    }
    if (j < cnt) {
        const int2 e0 = __ldg((const int2*)bkt4 + j);
        const uint2 u0 = *(const uint2*)(sp + (size_t)e0.x * D);
        accp(u0, (uint32_t)e0.y, p0a, p1a);
    }

    // combine sets
    asm("add.rn.f32x2 %0, %0, %1;" : "+l"(p0a) : "l"(p0b));
    asm("add.rn.f32x2 %0, %0, %1;" : "+l"(p1a) : "l"(p1b));

    F2U a0, a1; a0.u = p0a; a1.u = p1a;
    float4 o;
    o.x = tanh_fast(a0.f.x); o.y = tanh_fast(a0.f.y);
    o.z = tanh_fast(a1.f.x); o.w = tanh_fast(a1.f.y);
    *(float4*)(out + (size_t)r * D + lane * 4) = o;
}

// ---------------------------------------------------------------------------
// launch: fork at t=0:
//   s0: memset(cnt) -> fill
//   s1: wprep -> gemm
// join -> aggregate on s0.
// ---------------------------------------------------------------------------
extern "C" void kernel_launch(void* const* d_in, const int* in_sizes, int n_in,
                              void* d_out, int out_size)
{
    const float* x    = (const float*)d_in[0];
    const float* W    = (const float*)d_in[1];
    const int*   erow = (const int*)d_in[2];
    const int*   ecol = (const int*)d_in[3];
    const float* ev   = (const float*)d_in[4];
    float* out = (float*)d_out;

    const int n  = in_sizes[0] / D;
    const int nE = in_sizes[2];

    const int smem = 2 * 128 * ASTRIDE * (int)sizeof(__half);   // ~68 KB
    cudaFuncSetAttribute(gcn_gemm_kernel,
                         cudaFuncAttributeMaxDynamicSharedMemorySize, smem);

    void* cnt_ptr = nullptr;
    cudaGetSymbolAddress(&cnt_ptr, g_cnt);

    cudaStream_t s1;
    cudaStreamCreateWithFlags(&s1, cudaStreamNonBlocking);
    cudaEvent_t ev0, ev1;
    cudaEventCreateWithFlags(&ev0, cudaEventDisableTiming);
    cudaEventCreateWithFlags(&ev1, cudaEventDisableTiming);

    // fork marker at stream-0 head
    cudaEventRecord(ev0, 0);
    cudaStreamWaitEvent(s1, ev0, 0);

    // s1: W prep -> GEMM
    gcn_wprep_kernel<<<(D * D + 255) / 256, 256, 0, s1>>>(W);
    gcn_gemm_kernel<<<(n + 127) / 128, 256, smem, s1>>>(x, n);
    cudaEventRecord(ev1, s1);

    // s0: zero counts -> fill buckets
    cudaMemsetAsync(cnt_ptr, 0, (size_t)n * sizeof(int), 0);
    {
        const int q = (nE + 3) >> 2;
        gcn_fill_kernel<<<(q + 255) / 256, 256>>>(erow, ecol, ev, nE);
    }

    // join, aggregate
    cudaStreamWaitEvent(0, ev1, 0);
    gcn_aggregate_kernel<<<(n + 7) / 8, 256>>>(out, n);

    cudaEventDestroy(ev0);
    cudaEventDestroy(ev1);
    cudaStreamDestroy(s1);
}

// round 14
// speedup vs baseline: 1.0903x; 1.0903x over previous
#include <cuda_runtime.h>
#include <cuda_fp16.h>
#include <math.h>
#include <stdint.h>

#define D 128
#define NMAX 100000
#define EMAX 1600000
#define BCAP 64          // fixed bucket capacity (Poisson(16); P(overflow)~2e-13)

// ---- device scratch (no allocations allowed) -------------------------------
__device__ __half g_support_h[(size_t)NMAX * D];     // 25.6 MB fp16 support
__device__ int    g_cnt[NMAX];                       // bucket fill counts
__device__ int2   g_bkt[(size_t)NMAX * BCAP];        // 51.2 MB (col, val-bits)

// ---------------------------------------------------------------------------
__device__ __forceinline__ uint32_t smem_u32(const void* p) {
    uint32_t a;
    asm("{ .reg .u64 t; cvta.to.shared.u64 t, %1; cvt.u32.u64 %0, t; }"
        : "=r"(a) : "l"(p));
    return a;
}
__device__ __forceinline__ float tanh_fast(float x) {
    float y;
    asm("tanh.approx.f32 %0, %1;" : "=f"(y) : "f"(x));
    return y;
}
union F2U { float2 f; unsigned long long u; };

// ---------------------------------------------------------------------------
// prep: zero g_cnt (CSR-path only; GEMM has no dependency on it)
// ---------------------------------------------------------------------------
__global__ void gcn_prep_kernel(int n)
{
    const int i = blockIdx.x * blockDim.x + threadIdx.x;
    if (i < n) g_cnt[i] = 0;
}

// ---------------------------------------------------------------------------
// GEMM: support = fp16( x @ W ) via HMMA mma.sync.m16n8k16.
// W conversion fp32->fp16 inlined into staging (no prep dependency).
// ---------------------------------------------------------------------------
#define ASTRIDE 136

__global__ void __launch_bounds__(256)
gcn_gemm_kernel(const float* __restrict__ x, const float* __restrict__ W, int n)
{
    extern __shared__ __half sh[];
    __half* As = sh;                    // 128 * 136
    __half* Ws = sh + 128 * ASTRIDE;    // 128 * 136

    const int tid  = threadIdx.x;
    const int lane = tid & 31;
    const int warp = tid >> 5;
    const int row0 = blockIdx.x * 128;

    // stage x tile (fp32 -> fp16): thread = (row, half-row of 64 cols)
    {
        const int r = tid >> 1;
        const int h = tid & 1;
        const bool valid = (row0 + r) < n;
        const float4* src = (const float4*)(x + (size_t)(row0 + r) * D + h * 64);
        uint4* dst = (uint4*)(As + r * ASTRIDE + h * 64);
        #pragma unroll
        for (int g = 0; g < 8; g++) {
            float4 v0 = make_float4(0.f, 0.f, 0.f, 0.f), v1 = v0;
            if (valid) { v0 = src[2 * g]; v1 = src[2 * g + 1]; }
            uint4 o;
            __half2 t;
            t = __float22half2_rn(make_float2(v0.x, v0.y)); o.x = *(uint32_t*)&t;
            t = __float22half2_rn(make_float2(v0.z, v0.w)); o.y = *(uint32_t*)&t;
            t = __float22half2_rn(make_float2(v1.x, v1.y)); o.z = *(uint32_t*)&t;
            t = __float22half2_rn(make_float2(v1.z, v1.w)); o.w = *(uint32_t*)&t;
            dst[g] = o;
        }
    }
    // stage W tile (fp32 -> fp16 inline; W is L2-resident after first CTAs)
    {
        const int r = tid >> 1;
        const int h = tid & 1;
        const float4* src = (const float4*)(W + (size_t)r * D + h * 64);
        uint4* dst = (uint4*)(Ws + r * ASTRIDE + h * 64);
        #pragma unroll
        for (int g = 0; g < 8; g++) {
            const float4 v0 = src[2 * g];
            const float4 v1 = src[2 * g + 1];
            uint4 o;
            __half2 t;
            t = __float22half2_rn(make_float2(v0.x, v0.y)); o.x = *(uint32_t*)&t;
            t = __float22half2_rn(make_float2(v0.z, v0.w)); o.y = *(uint32_t*)&t;
            t = __float22half2_rn(make_float2(v1.x, v1.y)); o.z = *(uint32_t*)&t;
            t = __float22half2_rn(make_float2(v1.z, v1.w)); o.w = *(uint32_t*)&t;
            dst[g] = o;
        }
    }
    __syncthreads();

    float acc[16][4];
    #pragma unroll
    for (int j = 0; j < 16; j++)
        acc[j][0] = acc[j][1] = acc[j][2] = acc[j][3] = 0.f;

    const int ar = warp * 16 + (lane & 15);
    const int ac8 = (lane >> 4) * 8;

    #pragma unroll
    for (int ks = 0; ks < 8; ks++) {
        const int k0 = ks * 16;
        uint32_t a0, a1, a2, a3;
        {
            const uint32_t addr = smem_u32(As + ar * ASTRIDE + k0 + ac8);
            asm volatile("ldmatrix.sync.aligned.m8n8.x4.shared.b16 {%0,%1,%2,%3}, [%4];"
                         : "=r"(a0), "=r"(a1), "=r"(a2), "=r"(a3) : "r"(addr));
        }
        const uint32_t baddr0 = smem_u32(Ws + (k0 + (lane & 15)) * ASTRIDE + ac8);
        #pragma unroll
        for (int j2 = 0; j2 < 8; j2++) {
            uint32_t b0, b1, b2, b3;
            asm volatile("ldmatrix.sync.aligned.m8n8.x4.trans.shared.b16 {%0,%1,%2,%3}, [%4];"
                         : "=r"(b0), "=r"(b1), "=r"(b2), "=r"(b3)
                         : "r"(baddr0 + j2 * 32));
            float* c0 = acc[2 * j2];
            float* c1 = acc[2 * j2 + 1];
            asm volatile(
                "mma.sync.aligned.m16n8k16.row.col.f32.f16.f16.f32 "
                "{%0,%1,%2,%3}, {%4,%5,%6,%7}, {%8,%9}, {%0,%1,%2,%3};"
                : "+f"(c0[0]), "+f"(c0[1]), "+f"(c0[2]), "+f"(c0[3])
                : "r"(a0), "r"(a1), "r"(a2), "r"(a3), "r"(b0), "r"(b1));
            asm volatile(
                "mma.sync.aligned.m16n8k16.row.col.f32.f16.f16.f32 "
                "{%0,%1,%2,%3}, {%4,%5,%6,%7}, {%8,%9}, {%0,%1,%2,%3};"
                : "+f"(c1[0]), "+f"(c1[1]), "+f"(c1[2]), "+f"(c1[3])
                : "r"(a0), "r"(a1), "r"(a2), "r"(a3), "r"(b2), "r"(b3));
        }
    }

    const int rA = row0 + warp * 16 + (lane >> 2);
    const int cB = (lane & 3) * 2;
    #pragma unroll
    for (int j = 0; j < 16; j++) {
        const int n0 = j * 8;
        if (rA < n) {
            __half2 h = __float22half2_rn(make_float2(acc[j][0], acc[j][1]));
            *(__half2*)(g_support_h + (size_t)rA * D + n0 + cB) = h;
        }
        if (rA + 8 < n) {
            __half2 h = __float22half2_rn(make_float2(acc[j][2], acc[j][3]));
            *(__half2*)(g_support_h + (size_t)(rA + 8) * D + n0 + cB) = h;
        }
    }
}

// ---------------------------------------------------------------------------
// fill: direct bucket scatter, 2 independent edges per thread (R12 version)
// ---------------------------------------------------------------------------
__global__ void gcn_fill_kernel(const int* __restrict__ erow,
                                const int* __restrict__ ecol,
                                const float* __restrict__ eval_, int nE)
{
    const int half = (nE + 1) >> 1;
    const int e = blockIdx.x * blockDim.x + threadIdx.x;
    if (e >= half) return;
    const int e2 = e + half;
    const bool v2 = e2 < nE;

    const int r0 = __ldg(&erow[e]);
    const int c0 = __ldg(&ecol[e]);
    const float f0 = __ldg(&eval_[e]);
    int r1 = 0, c1 = 0; float f1 = 0.f;
    if (v2) { r1 = __ldg(&erow[e2]); c1 = __ldg(&ecol[e2]); f1 = __ldg(&eval_[e2]); }

    const int p0 = atomicAdd(&g_cnt[r0], 1);
    int p1 = 0;
    if (v2) p1 = atomicAdd(&g_cnt[r1], 1);

    g_bkt[(size_t)r0 * BCAP + p0] = make_int2(c0, __float_as_int(f0));
    if (v2) g_bkt[(size_t)r1 * BCAP + p1] = make_int2(c1, __float_as_int(f1));
}

// ---------------------------------------------------------------------------
// Aggregate v3 (measured best: 51.7us): warp per row, full warp per edge,
// lane owns 4 cols, FFMA2 accum, 4-edge unroll, fused tanh.approx.
// ---------------------------------------------------------------------------
__device__ __forceinline__ void accp(const uint2 u, const int vbits,
                                     unsigned long long& p0,
                                     unsigned long long& p1)
{
    const float v = __int_as_float(vbits);
    F2U vv; vv.f = make_float2(v, v);
    F2U f0; f0.f = __half22float2(*(const __half2*)&u.x);
    F2U f1; f1.f = __half22float2(*(const __half2*)&u.y);
    asm("fma.rn.f32x2 %0, %1, %2, %0;" : "+l"(p0) : "l"(vv.u), "l"(f0.u));
    asm("fma.rn.f32x2 %0, %1, %2, %0;" : "+l"(p1) : "l"(vv.u), "l"(f1.u));
}

__global__ void __launch_bounds__(256)
gcn_aggregate_kernel(float* __restrict__ out, int n)
{
    const int r = blockIdx.x * 8 + (threadIdx.x >> 5);
    const int lane = threadIdx.x & 31;
    if (r >= n) return;

    int cnt = g_cnt[r];
    if (cnt > BCAP) cnt = BCAP;
    const int2* bkt = g_bkt + (size_t)r * BCAP;
    const __half* sp = g_support_h + lane * 4;       // lane's 4-col slice

    unsigned long long p0 = 0ull, p1 = 0ull;         // {c0,c1},{c2,c3} fp32 pairs

    int j = 0;
    for (; j + 4 <= cnt; j += 4) {
        const int2 e0 = __ldg(&bkt[j]);              // uniform -> broadcast
        const int2 e1 = __ldg(&bkt[j + 1]);
        const int2 e2 = __ldg(&bkt[j + 2]);
        const int2 e3 = __ldg(&bkt[j + 3]);
        const uint2 u0 = *(const uint2*)(sp + (size_t)e0.x * D);
        const uint2 u1 = *(const uint2*)(sp + (size_t)e1.x * D);
        const uint2 u2 = *(const uint2*)(sp + (size_t)e2.x * D);
        const uint2 u3 = *(const uint2*)(sp + (size_t)e3.x * D);
        accp(u0, e0.y, p0, p1);
        accp(u1, e1.y, p0, p1);
        accp(u2, e2.y, p0, p1);
        accp(u3, e3.y, p0, p1);
    }
    for (; j < cnt; j++) {
        const int2 e0 = __ldg(&bkt[j]);
        const uint2 u0 = *(const uint2*)(sp + (size_t)e0.x * D);
        accp(u0, e0.y, p0, p1);
    }

    F2U a0, a1; a0.u = p0; a1.u = p1;
    float4 o;
    o.x = tanh_fast(a0.f.x); o.y = tanh_fast(a0.f.y);
    o.z = tanh_fast(a1.f.x); o.w = tanh_fast(a1.f.y);
    *(float4*)(out + (size_t)r * D + lane * 4) = o;
}

// ---------------------------------------------------------------------------
// launch: fork at t=0:
//   s1: GEMM (no dependencies)
//   s0: prep(zero cnt) -> fill
// join -> aggregate on s0.
// ---------------------------------------------------------------------------
extern "C" void kernel_launch(void* const* d_in, const int* in_sizes, int n_in,
                              void* d_out, int out_size)
{
    const float* x    = (const float*)d_in[0];
    const float* W    = (const float*)d_in[1];
    const int*   erow = (const int*)d_in[2];
    const int*   ecol = (const int*)d_in[3];
    const float* ev   = (const float*)d_in[4];
    float* out = (float*)d_out;

    const int n  = in_sizes[0] / D;
    const int nE = in_sizes[2];

    const int smem = 2 * 128 * ASTRIDE * (int)sizeof(__half);   // ~68 KB
    cudaFuncSetAttribute(gcn_gemm_kernel,
                         cudaFuncAttributeMaxDynamicSharedMemorySize, smem);

    cudaStream_t s1;
    cudaStreamCreateWithFlags(&s1, cudaStreamNonBlocking);
    cudaEvent_t ev0, ev1;
    cudaEventCreateWithFlags(&ev0, cudaEventDisableTiming);
    cudaEventCreateWithFlags(&ev1, cudaEventDisableTiming);

    // fork marker at stream-0 head
    cudaEventRecord(ev0, 0);
    cudaStreamWaitEvent(s1, ev0, 0);

    // s1: GEMM (independent of CSR path)
    gcn_gemm_kernel<<<(n + 127) / 128, 256, smem, s1>>>(x, W, n);
    cudaEventRecord(ev1, s1);

    // s0: zero counts -> fill buckets
    gcn_prep_kernel<<<(n + 255) / 256, 256>>>(n);
    {
        const int half = (nE + 1) >> 1;
        gcn_fill_kernel<<<(half + 255) / 256, 256>>>(erow, ecol, ev, nE);
    }

    // join, aggregate
    cudaStreamWaitEvent(0, ev1, 0);
    gcn_aggregate_kernel<<<(n + 7) / 8, 256>>>(out, n);

    cudaEventDestroy(ev0);
    cudaEventDestroy(ev1);
    cudaStreamDestroy(s1);
}

// round 15
// speedup vs baseline: 1.3234x; 1.2138x over previous
#include <cuda_runtime.h>
#include <cuda_fp16.h>
#include <math.h>
#include <stdint.h>

#define D 128
#define NMAX 100000
#define EMAX 1600000
#define BCAP 64          // fixed bucket capacity (Poisson(16); P(overflow)~2e-13)

// ---- device scratch (no allocations allowed) -------------------------------
__device__ __half g_support_h[(size_t)NMAX * D];     // 25.6 MB fp16 support
__device__ int    g_cnt[NMAX];                       // bucket fill counts
__device__ int2   g_bkt[(size_t)NMAX * BCAP];        // 51.2 MB (col, val-bits)
__device__ __half g_Wh[D * D];                       // fp16 W, [k][n]

// ---------------------------------------------------------------------------
__device__ __forceinline__ uint32_t smem_u32(const void* p) {
    uint32_t a;
    asm("{ .reg .u64 t; cvta.to.shared.u64 t, %1; cvt.u32.u64 %0, t; }"
        : "=r"(a) : "l"(p));
    return a;
}
__device__ __forceinline__ float tanh_fast(float x) {
    float y;
    asm("tanh.approx.f32 %0, %1;" : "=f"(y) : "f"(x));
    return y;
}
union F2U { float2 f; unsigned long long u; };

// ---------------------------------------------------------------------------
// prep (R12): zero g_cnt + W fp32->fp16, fused one-shot
// ---------------------------------------------------------------------------
__global__ void gcn_prep_kernel(const float* __restrict__ W, int n)
{
    const int i = blockIdx.x * blockDim.x + threadIdx.x;
    if (i < n) g_cnt[i] = 0;
    if (i < D * D) g_Wh[i] = __float2half_rn(W[i]);
}

// ---------------------------------------------------------------------------
// GEMM: support = fp16( x @ W ) via HMMA mma.sync.m16n8k16.
// R15 change: COALESCED staging. x: warp reads 512B contiguous, writes one
// full smem row (256B) per warp-iteration. W: linear copy from g_Wh.
// ---------------------------------------------------------------------------
#define ASTRIDE 136

__global__ void __launch_bounds__(256)
gcn_gemm_kernel(const float* __restrict__ x, int n)
{
    extern __shared__ __half sh[];
    __half* As = sh;                    // 128 * 136
    __half* Ws = sh + 128 * ASTRIDE;    // 128 * 136

    const int tid  = threadIdx.x;
    const int lane = tid & 31;
    const int warp = tid >> 5;
    const int row0 = blockIdx.x * 128;

    // ---- stage x (coalesced): float4 index i = tid + 256*it, it = 0..15
    // row = i>>5 (uniform per warp), c4 = i&31. 16B fp32 -> 8B fp16 (uint2).
    {
        const float4* src = (const float4*)(x + (size_t)row0 * D);
        const int maxv = (n - row0) * (D / 4);       // valid float4 count
        #pragma unroll
        for (int it = 0; it < 16; it++) {
            const int i = tid + 256 * it;
            float4 v = make_float4(0.f, 0.f, 0.f, 0.f);
            if (i < maxv) v = src[i];
            const int row = i >> 5;
            const int c4 = i & 31;
            uint2 o;
            __half2 t;
            t = __float22half2_rn(make_float2(v.x, v.y)); o.x = *(uint32_t*)&t;
            t = __float22half2_rn(make_float2(v.z, v.w)); o.y = *(uint32_t*)&t;
            *(uint2*)(As + row * ASTRIDE + c4 * 4) = o;
        }
    }
    // ---- stage W (coalesced copy of pre-converted fp16): uint4 i = tid+256*it
    {
        const uint4* src = (const uint4*)g_Wh;       // 2048 uint4
        #pragma unroll
        for (int it = 0; it < 8; it++) {
            const int i = tid + 256 * it;
            const int row = i >> 4;                  // 16 uint4 per 128-half row
            const int c16 = i & 15;
            *(uint4*)(Ws + row * ASTRIDE + c16 * 8) = src[i];
        }
    }
    __syncthreads();

    float acc[16][4];
    #pragma unroll
    for (int j = 0; j < 16; j++)
        acc[j][0] = acc[j][1] = acc[j][2] = acc[j][3] = 0.f;

    const int ar = warp * 16 + (lane & 15);
    const int ac8 = (lane >> 4) * 8;

    #pragma unroll
    for (int ks = 0; ks < 8; ks++) {
        const int k0 = ks * 16;
        uint32_t a0, a1, a2, a3;
        {
            const uint32_t addr = smem_u32(As + ar * ASTRIDE + k0 + ac8);
            asm volatile("ldmatrix.sync.aligned.m8n8.x4.shared.b16 {%0,%1,%2,%3}, [%4];"
                         : "=r"(a0), "=r"(a1), "=r"(a2), "=r"(a3) : "r"(addr));
        }
        const uint32_t baddr0 = smem_u32(Ws + (k0 + (lane & 15)) * ASTRIDE + ac8);
        #pragma unroll
        for (int j2 = 0; j2 < 8; j2++) {
            uint32_t b0, b1, b2, b3;
            asm volatile("ldmatrix.sync.aligned.m8n8.x4.trans.shared.b16 {%0,%1,%2,%3}, [%4];"
                         : "=r"(b0), "=r"(b1), "=r"(b2), "=r"(b3)
                         : "r"(baddr0 + j2 * 32));
            float* c0 = acc[2 * j2];
            float* c1 = acc[2 * j2 + 1];
            asm volatile(
                "mma.sync.aligned.m16n8k16.row.col.f32.f16.f16.f32 "
                "{%0,%1,%2,%3}, {%4,%5,%6,%7}, {%8,%9}, {%0,%1,%2,%3};"
                : "+f"(c0[0]), "+f"(c0[1]), "+f"(c0[2]), "+f"(c0[3])
                : "r"(a0), "r"(a1), "r"(a2), "r"(a3), "r"(b0), "r"(b1));
            asm volatile(
                "mma.sync.aligned.m16n8k16.row.col.f32.f16.f16.f32 "
                "{%0,%1,%2,%3}, {%4,%5,%6,%7}, {%8,%9}, {%0,%1,%2,%3};"
                : "+f"(c1[0]), "+f"(c1[1]), "+f"(c1[2]), "+f"(c1[3])
                : "r"(a0), "r"(a1), "r"(a2), "r"(a3), "r"(b2), "r"(b3));
        }
    }

    const int rA = row0 + warp * 16 + (lane >> 2);
    const int cB = (lane & 3) * 2;
    #pragma unroll
    for (int j = 0; j < 16; j++) {
        const int n0 = j * 8;
        if (rA < n) {
            __half2 h = __float22half2_rn(make_float2(acc[j][0], acc[j][1]));
            *(__half2*)(g_support_h + (size_t)rA * D + n0 + cB) = h;
        }
        if (rA + 8 < n) {
            __half2 h = __float22half2_rn(make_float2(acc[j][2], acc[j][3]));
            *(__half2*)(g_support_h + (size_t)(rA + 8) * D + n0 + cB) = h;
        }
    }
}

// ---------------------------------------------------------------------------
// fill (R12): direct bucket scatter, 2 independent edges per thread
// ---------------------------------------------------------------------------
__global__ void gcn_fill_kernel(const int* __restrict__ erow,
                                const int* __restrict__ ecol,
                                const float* __restrict__ eval_, int nE)
{
    const int half = (nE + 1) >> 1;
    const int e = blockIdx.x * blockDim.x + threadIdx.x;
    if (e >= half) return;
    const int e2 = e + half;
    const bool v2 = e2 < nE;

    const int r0 = __ldg(&erow[e]);
    const int c0 = __ldg(&ecol[e]);
    const float f0 = __ldg(&eval_[e]);
    int r1 = 0, c1 = 0; float f1 = 0.f;
    if (v2) { r1 = __ldg(&erow[e2]); c1 = __ldg(&ecol[e2]); f1 = __ldg(&eval_[e2]); }

    const int p0 = atomicAdd(&g_cnt[r0], 1);
    int p1 = 0;
    if (v2) p1 = atomicAdd(&g_cnt[r1], 1);

    g_bkt[(size_t)r0 * BCAP + p0] = make_int2(c0, __float_as_int(f0));
    if (v2) g_bkt[(size_t)r1 * BCAP + p1] = make_int2(c1, __float_as_int(f1));
}

// ---------------------------------------------------------------------------
// Aggregate v3 (R12, measured 51.7us): warp per row, full warp per edge,
// lane owns 4 cols, FFMA2 accum, 4-edge unroll, fused tanh.approx.
// ---------------------------------------------------------------------------
__device__ __forceinline__ void accp(const uint2 u, const int vbits,
                                     unsigned long long& p0,
                                     unsigned long long& p1)
{
    const float v = __int_as_float(vbits);
    F2U vv; vv.f = make_float2(v, v);
    F2U f0; f0.f = __half22float2(*(const __half2*)&u.x);
    F2U f1; f1.f = __half22float2(*(const __half2*)&u.y);
    asm("fma.rn.f32x2 %0, %1, %2, %0;" : "+l"(p0) : "l"(vv.u), "l"(f0.u));
    asm("fma.rn.f32x2 %0, %1, %2, %0;" : "+l"(p1) : "l"(vv.u), "l"(f1.u));
}

__global__ void __launch_bounds__(256)
gcn_aggregate_kernel(float* __restrict__ out, int n)
{
    const int r = blockIdx.x * 8 + (threadIdx.x >> 5);
    const int lane = threadIdx.x & 31;
    if (r >= n) return;

    int cnt = g_cnt[r];
    if (cnt > BCAP) cnt = BCAP;
    const int2* bkt = g_bkt + (size_t)r * BCAP;
    const __half* sp = g_support_h + lane * 4;       // lane's 4-col slice

    unsigned long long p0 = 0ull, p1 = 0ull;         // {c0,c1},{c2,c3} fp32 pairs

    int j = 0;
    for (; j + 4 <= cnt; j += 4) {
        const int2 e0 = __ldg(&bkt[j]);              // uniform -> broadcast
        const int2 e1 = __ldg(&bkt[j + 1]);
        const int2 e2 = __ldg(&bkt[j + 2]);
        const int2 e3 = __ldg(&bkt[j + 3]);
        const uint2 u0 = *(const uint2*)(sp + (size_t)e0.x * D);
        const uint2 u1 = *(const uint2*)(sp + (size_t)e1.x * D);
        const uint2 u2 = *(const uint2*)(sp + (size_t)e2.x * D);
        const uint2 u3 = *(const uint2*)(sp + (size_t)e3.x * D);
        accp(u0, e0.y, p0, p1);
        accp(u1, e1.y, p0, p1);
        accp(u2, e2.y, p0, p1);
        accp(u3, e3.y, p0, p1);
    }
    for (; j < cnt; j++) {
        const int2 e0 = __ldg(&bkt[j]);
        const uint2 u0 = *(const uint2*)(sp + (size_t)e0.x * D);
        accp(u0, e0.y, p0, p1);
    }

    F2U a0, a1; a0.u = p0; a1.u = p1;
    float4 o;
    o.x = tanh_fast(a0.f.x); o.y = tanh_fast(a0.f.y);
    o.z = tanh_fast(a1.f.x); o.w = tanh_fast(a1.f.y);
    *(float4*)(out + (size_t)r * D + lane * 4) = o;
}

// ---------------------------------------------------------------------------
// launch (R12 structure): prep -> fork { GEMM on s1 } || { fill } -> join
//                         -> aggregate
// ---------------------------------------------------------------------------
extern "C" void kernel_launch(void* const* d_in, const int* in_sizes, int n_in,
                              void* d_out, int out_size)
{
    const float* x    = (const float*)d_in[0];
    const float* W    = (const float*)d_in[1];
    const int*   erow = (const int*)d_in[2];
    const int*   ecol = (const int*)d_in[3];
    const float* ev   = (const float*)d_in[4];
    float* out = (float*)d_out;

    const int n  = in_sizes[0] / D;
    const int nE = in_sizes[2];

    const int smem = 2 * 128 * ASTRIDE * (int)sizeof(__half);   // ~68 KB
    cudaFuncSetAttribute(gcn_gemm_kernel,
                         cudaFuncAttributeMaxDynamicSharedMemorySize, smem);

    cudaStream_t s1;
    cudaStreamCreateWithFlags(&s1, cudaStreamNonBlocking);
    cudaEvent_t ev0, ev1;
    cudaEventCreateWithFlags(&ev0, cudaEventDisableTiming);
    cudaEventCreateWithFlags(&ev1, cudaEventDisableTiming);

    // prep (zero cnt + W->fp16) — GEMM depends on g_Wh
    gcn_prep_kernel<<<(n + 255) / 256, 256>>>(W, n);

    // fork: GEMM on s1
    cudaEventRecord(ev0, 0);
    cudaStreamWaitEvent(s1, ev0, 0);
    gcn_gemm_kernel<<<(n + 127) / 128, 256, smem, s1>>>(x, n);
    cudaEventRecord(ev1, s1);

    // s0: fill buckets
    {
        const int half = (nE + 1) >> 1;
        gcn_fill_kernel<<<(half + 255) / 256, 256>>>(erow, ecol, ev, nE);
    }

    // join, aggregate
    cudaStreamWaitEvent(0, ev1, 0);
    gcn_aggregate_kernel<<<(n + 7) / 8, 256>>>(out, n);

    cudaEventDestroy(ev0);
    cudaEventDestroy(ev1);
    cudaStreamDestroy(s1);
}

// round 17
// speedup vs baseline: 1.4255x; 1.0771x over previous
#include <cuda_runtime.h>
#include <cuda_fp16.h>
#include <math.h>
#include <stdint.h>

#define D 128
#define NMAX 100000
#define EMAX 1600000
#define BCAP 64          // fixed bucket capacity (Poisson(16); P(overflow)~2e-13)

// ---- device scratch (no allocations allowed) -------------------------------
__device__ __half g_support_h[(size_t)NMAX * D];     // 25.6 MB fp16 support
__device__ int    g_cnt[NMAX];                       // bucket fill counts
__device__ int2   g_bkt[(size_t)NMAX * BCAP];        // 51.2 MB (col, val-bits)
__device__ __half g_Wh[D * D];                       // fp16 W, [k][n]

// ---------------------------------------------------------------------------
__device__ __forceinline__ uint32_t smem_u32(const void* p) {
    uint32_t a;
    asm("{ .reg .u64 t; cvta.to.shared.u64 t, %1; cvt.u32.u64 %0, t; }"
        : "=r"(a) : "l"(p));
    return a;
}
__device__ __forceinline__ float tanh_fast(float x) {
    float y;
    asm("tanh.approx.f32 %0, %1;" : "=f"(y) : "f"(x));
    return y;
}
union F2U { float2 f; unsigned long long u; };

// ---------------------------------------------------------------------------
// prep: zero g_cnt + W fp32->fp16, fused one-shot
// ---------------------------------------------------------------------------
__global__ void gcn_prep_kernel(const float* __restrict__ W, int n)
{
    const int i = blockIdx.x * blockDim.x + threadIdx.x;
    if (i < n) g_cnt[i] = 0;
    if (i < D * D) g_Wh[i] = __float2half_rn(W[i]);
}

// ---------------------------------------------------------------------------
// GEMM: support = fp16( x @ W ) via HMMA mma.sync.m16n8k16.
// R16: epilogue through smem (conflict-free STS) -> coalesced uint4 STG.
// ---------------------------------------------------------------------------
#define ASTRIDE 136

__global__ void __launch_bounds__(256)
gcn_gemm_kernel(const float* __restrict__ x, int n)
{
    extern __shared__ __half sh[];
    __half* As = sh;                    // 128 * 136 (reused for C in epilogue)
    __half* Ws = sh + 128 * ASTRIDE;    // 128 * 136

    const int tid  = threadIdx.x;
    const int lane = tid & 31;
    const int warp = tid >> 5;
    const int row0 = blockIdx.x * 128;

    // ---- stage x (coalesced): float4 i = tid + 256*it
    {
        const float4* src = (const float4*)(x + (size_t)row0 * D);
        const int maxv = (n - row0) * (D / 4);
        #pragma unroll
        for (int it = 0; it < 16; it++) {
            const int i = tid + 256 * it;
            float4 v = make_float4(0.f, 0.f, 0.f, 0.f);
            if (i < maxv) v = src[i];
            const int row = i >> 5;
            const int c4 = i & 31;
            uint2 o;
            __half2 t;
            t = __float22half2_rn(make_float2(v.x, v.y)); o.x = *(uint32_t*)&t;
            t = __float22half2_rn(make_float2(v.z, v.w)); o.y = *(uint32_t*)&t;
            *(uint2*)(As + row * ASTRIDE + c4 * 4) = o;
        }
    }
    // ---- stage W (coalesced copy of pre-converted fp16)
    {
        const uint4* src = (const uint4*)g_Wh;
        #pragma unroll
        for (int it = 0; it < 8; it++) {
            const int i = tid + 256 * it;
            const int row = i >> 4;
            const int c16 = i & 15;
            *(uint4*)(Ws + row * ASTRIDE + c16 * 8) = src[i];
        }
    }
    __syncthreads();

    float acc[16][4];
    #pragma unroll
    for (int j = 0; j < 16; j++)
        acc[j][0] = acc[j][1] = acc[j][2] = acc[j][3] = 0.f;

    const int ar = warp * 16 + (lane & 15);
    const int ac8 = (lane >> 4) * 8;

    #pragma unroll
    for (int ks = 0; ks < 8; ks++) {
        const int k0 = ks * 16;
        uint32_t a0, a1, a2, a3;
        {
            const uint32_t addr = smem_u32(As + ar * ASTRIDE + k0 + ac8);
            asm volatile("ldmatrix.sync.aligned.m8n8.x4.shared.b16 {%0,%1,%2,%3}, [%4];"
                         : "=r"(a0), "=r"(a1), "=r"(a2), "=r"(a3) : "r"(addr));
        }
        const uint32_t baddr0 = smem_u32(Ws + (k0 + (lane & 15)) * ASTRIDE + ac8);
        #pragma unroll
        for (int j2 = 0; j2 < 8; j2++) {
            uint32_t b0, b1, b2, b3;
            asm volatile("ldmatrix.sync.aligned.m8n8.x4.trans.shared.b16 {%0,%1,%2,%3}, [%4];"
                         : "=r"(b0), "=r"(b1), "=r"(b2), "=r"(b3)
                         : "r"(baddr0 + j2 * 32));
            float* c0 = acc[2 * j2];
            float* c1 = acc[2 * j2 + 1];
            asm volatile(
                "mma.sync.aligned.m16n8k16.row.col.f32.f16.f16.f32 "
                "{%0,%1,%2,%3}, {%4,%5,%6,%7}, {%8,%9}, {%0,%1,%2,%3};"
                : "+f"(c0[0]), "+f"(c0[1]), "+f"(c0[2]), "+f"(c0[3])
                : "r"(a0), "r"(a1), "r"(a2), "r"(a3), "r"(b0), "r"(b1));
            asm volatile(
                "mma.sync.aligned.m16n8k16.row.col.f32.f16.f16.f32 "
                "{%0,%1,%2,%3}, {%4,%5,%6,%7}, {%8,%9}, {%0,%1,%2,%3};"
                : "+f"(c1[0]), "+f"(c1[1]), "+f"(c1[2]), "+f"(c1[3])
                : "r"(a0), "r"(a1), "r"(a2), "r"(a3), "r"(b2), "r"(b3));
        }
    }

    // ---- epilogue v2: fragments -> smem (conflict-free STS.32) ->
    //      coalesced uint4 stores.  C reuses the As region.
    __syncthreads();                       // all ldmatrix reads of As done
    {
        const int rloc = warp * 16 + (lane >> 2);     // local row of c0/c1
        const int cB = (lane & 3) * 2;
        #pragma unroll
        for (int j = 0; j < 16; j++) {
            const int n0 = j * 8;
            __half2 h0 = __float22half2_rn(make_float2(acc[j][0], acc[j][1]));
            __half2 h1 = __float22half2_rn(make_float2(acc[j][2], acc[j][3]));
            *(__half2*)(As + rloc * ASTRIDE + n0 + cB) = h0;
            *(__half2*)(As + (rloc + 8) * ASTRIDE + n0 + cB) = h1;
        }
    }
    __syncthreads();
    {
        // 128 rows x 128 halves -> uint4 i = tid + 256*it  (coalesced STG.128)
        #pragma unroll
        for (int it = 0; it < 8; it++) {
            const int i = tid + 256 * it;
            const int row = i >> 4;                  // 16 uint4 per row
            const int c16 = i & 15;
            if (row0 + row < n) {
                const uint4 v = *(const uint4*)(As + row * ASTRIDE + c16 * 8);
                ((uint4*)(g_support_h + (size_t)(row0 + row) * D))[c16] = v;
            }
        }
    }
}

// ---------------------------------------------------------------------------
// fill: direct bucket scatter, 2 independent edges per thread
// ---------------------------------------------------------------------------
__global__ void gcn_fill_kernel(const int* __restrict__ erow,
                                const int* __restrict__ ecol,
                                const float* __restrict__ eval_, int nE)
{
    const int half = (nE + 1) >> 1;
    const int e = blockIdx.x * blockDim.x + threadIdx.x;
    if (e >= half) return;
    const int e2 = e + half;
    const bool v2 = e2 < nE;

    const int r0 = __ldg(&erow[e]);
    const int c0 = __ldg(&ecol[e]);
    const float f0 = __ldg(&eval_[e]);
    int r1 = 0, c1 = 0; float f1 = 0.f;
    if (v2) { r1 = __ldg(&erow[e2]); c1 = __ldg(&ecol[e2]); f1 = __ldg(&eval_[e2]); }

    const int p0 = atomicAdd(&g_cnt[r0], 1);
    int p1 = 0;
    if (v2) p1 = atomicAdd(&g_cnt[r1], 1);

    g_bkt[(size_t)r0 * BCAP + p0] = make_int2(c0, __float_as_int(f0));
    if (v2) g_bkt[(size_t)r1 * BCAP + p1] = make_int2(c1, __float_as_int(f1));
}

// ---------------------------------------------------------------------------
// Aggregate v3 + R16 scheduling: 64-thread blocks (2 warps, 2 rows) so block
// runtime is max-of-2 degrees, not max-of-8 -> scheduler rebalances.
// ---------------------------------------------------------------------------
__device__ __forceinline__ void accp(const uint2 u, const int vbits,
                                     unsigned long long& p0,
                                     unsigned long long& p1)
{
    const float v = __int_as_float(vbits);
    F2U vv; vv.f = make_float2(v, v);
    F2U f0; f0.f = __half22float2(*(const __half2*)&u.x);
    F2U f1; f1.f = __half22float2(*(const __half2*)&u.y);
    asm("fma.rn.f32x2 %0, %1, %2, %0;" : "+l"(p0) : "l"(vv.u), "l"(f0.u));
    asm("fma.rn.f32x2 %0, %1, %2, %0;" : "+l"(p1) : "l"(vv.u), "l"(f1.u));
}

__global__ void __launch_bounds__(64)
gcn_aggregate_kernel(float* __restrict__ out, int n)
{
    const int r = blockIdx.x * 2 + (threadIdx.x >> 5);
    const int lane = threadIdx.x & 31;
    if (r >= n) return;

    int cnt = g_cnt[r];
    if (cnt > BCAP) cnt = BCAP;
    const int2* bkt = g_bkt + (size_t)r * BCAP;
    const __half* sp = g_support_h + lane * 4;       // lane's 4-col slice

    unsigned long long p0 = 0ull, p1 = 0ull;         // {c0,c1},{c2,c3} fp32 pairs

    int j = 0;
    for (; j + 4 <= cnt; j += 4) {
        const int2 e0 = __ldg(&bkt[j]);              // uniform -> broadcast
        const int2 e1 = __ldg(&bkt[j + 1]);
        const int2 e2 = __ldg(&bkt[j + 2]);
        const int2 e3 = __ldg(&bkt[j + 3]);
        const uint2 u0 = *(const uint2*)(sp + (size_t)e0.x * D);
        const uint2 u1 = *(const uint2*)(sp + (size_t)e1.x * D);
        const uint2 u2 = *(const uint2*)(sp + (size_t)e2.x * D);
        const uint2 u3 = *(const uint2*)(sp + (size_t)e3.x * D);
        accp(u0, e0.y, p0, p1);
        accp(u1, e1.y, p0, p1);
        accp(u2, e2.y, p0, p1);
        accp(u3, e3.y, p0, p1);
    }
    for (; j < cnt; j++) {
        const int2 e0 = __ldg(&bkt[j]);
        const uint2 u0 = *(const uint2*)(sp + (size_t)e0.x * D);
        accp(u0, e0.y, p0, p1);
    }

    F2U a0, a1; a0.u = p0; a1.u = p1;
    float4 o;
    o.x = tanh_fast(a0.f.x); o.y = tanh_fast(a0.f.y);
    o.z = tanh_fast(a1.f.x); o.w = tanh_fast(a1.f.y);
    *(float4*)(out + (size_t)r * D + lane * 4) = o;
}

// ---------------------------------------------------------------------------
// launch: prep -> fork { GEMM on s1 } || { fill } -> join -> aggregate
// ---------------------------------------------------------------------------
extern "C" void kernel_launch(void* const* d_in, const int* in_sizes, int n_in,
                              void* d_out, int out_size)
{
    const float* x    = (const float*)d_in[0];
    const float* W    = (const float*)d_in[1];
    const int*   erow = (const int*)d_in[2];
    const int*   ecol = (const int*)d_in[3];
    const float* ev   = (const float*)d_in[4];
    float* out = (float*)d_out;

    const int n  = in_sizes[0] / D;
    const int nE = in_sizes[2];

    const int smem = 2 * 128 * ASTRIDE * (int)sizeof(__half);   // ~68 KB
    cudaFuncSetAttribute(gcn_gemm_kernel,
                         cudaFuncAttributeMaxDynamicSharedMemorySize, smem);

    cudaStream_t s1;
    cudaStreamCreateWithFlags(&s1, cudaStreamNonBlocking);
    cudaEvent_t ev0, ev1;
    cudaEventCreateWithFlags(&ev0, cudaEventDisableTiming);
    cudaEventCreateWithFlags(&ev1, cudaEventDisableTiming);

    // prep (zero cnt + W->fp16) — GEMM depends on g_Wh
    gcn_prep_kernel<<<(n + 255) / 256, 256>>>(W, n);

    // fork: GEMM on s1
    cudaEventRecord(ev0, 0);
    cudaStreamWaitEvent(s1, ev0, 0);
    gcn_gemm_kernel<<<(n + 127) / 128, 256, smem, s1>>>(x, n);
    cudaEventRecord(ev1, s1);

    // s0: fill buckets
    {
        const int half = (nE + 1) >> 1;
        gcn_fill_kernel<<<(half + 255) / 256, 256>>>(erow, ecol, ev, nE);
    }

    // join, aggregate
    cudaStreamWaitEvent(0, ev1, 0);
    gcn_aggregate_kernel<<<(n + 1) / 2, 64>>>(out, n);

    cudaEventDestroy(ev0);
    cudaEventDestroy(ev1);
    cudaStreamDestroy(s1);
}